// round 12
// baseline (speedup 1.0000x reference)
#include <cuda_runtime.h>
#include <cuda_fp16.h>
#include <cstdint>

// Problem shape (fixed by the dataset instance)
#define NBATCH 32
#define EDIM   512
#define TDIM   512
#define M_ROWS 16384           // NBATCH*TDIM
#define NE     8192            // number of codes
#define NET    8388608         // NBATCH*EDIM*TDIM

#define CAP    32              // candidate cap per row (warp-sized)
#define MARGIN 2e-3f           // >= 2*(tf32 err) + fp16 q + bucket; validated

// ---- scratch (__device__ globals; no allocations allowed) ----
__device__ float  g_zz[M_ROWS];
__device__ float  g_see[NE];
__device__ float  g_zt[NET];            // tf32-pre-rounded z
__device__ float  g_et[NE * EDIM];      // tf32-pre-rounded emb
__device__ __half g_dhat[(size_t)M_ROWS * NE];  // 268MB approx distances
__device__ int    g_ccnt[M_ROWS];
__device__ int    g_cand[M_ROWS * CAP];
__device__ int    g_idx[M_ROWS];
__device__ int    g_counts[NE];
__device__ double g_loss;

// TF32 rounding (approximation path only)
__device__ __forceinline__ float tf32r(float x) {
    uint32_t u;
    asm("cvt.rna.tf32.f32 %0, %1;" : "=r"(u) : "f"(x));
    return __uint_as_float(u);
}

// m16n8k8 TF32 tensor-core MMA, fp32 accumulate
__device__ __forceinline__ void mma_tf32(float* c,
                                         const uint32_t* a,
                                         const uint32_t* b) {
    asm volatile(
        "mma.sync.aligned.m16n8k8.row.col.f32.tf32.tf32.f32 "
        "{%0,%1,%2,%3}, {%4,%5,%6,%7}, {%8,%9}, {%0,%1,%2,%3};"
        : "+f"(c[0]), "+f"(c[1]), "+f"(c[2]), "+f"(c[3])
        : "r"(a[0]), "r"(a[1]), "r"(a[2]), "r"(a[3]),
          "r"(b[0]), "r"(b[1]));
}

// cp.async 16B (L2->smem, bypasses L1)
__device__ __forceinline__ void cp_async16(void* smem, const void* gmem) {
    uint32_t s = (uint32_t)__cvta_generic_to_shared(smem);
    asm volatile("cp.async.cg.shared.global [%0], [%1], 16;"
                 :: "r"(s), "l"(gmem));
}
#define CP_COMMIT()  asm volatile("cp.async.commit_group;")
#define CP_WAIT(n)   asm volatile("cp.async.wait_group %0;" :: "n"(n))

// ============================================================
// Row sum-of-squares. FROZEN bit patterns (zz is part of the
// reference's tie bucketing; these exact kernels passed).
// ============================================================
__device__ __forceinline__ float row_sumsq(float x0, float x1,
                                           float* ws, int tid) {
    float v = __fadd_rn(__fmul_rn(x0, x0), __fmul_rn(x1, x1));
    #pragma unroll
    for (int o = 16; o >= 1; o >>= 1)
        v = __fadd_rn(v, __shfl_down_sync(0xffffffffu, v, o));
    if ((tid & 31) == 0) ws[tid >> 5] = v;
    __syncthreads();
    float r = 0.f;
    if (tid < 32) {
        float p = (tid < 8) ? ws[tid] : 0.f;
        #pragma unroll
        for (int o = 16; o >= 1; o >>= 1)
            p = __fadd_rn(p, __shfl_down_sync(0xffffffffu, p, o));
        r = p;
    }
    return r;
}

__global__ void see_kernel(const float* __restrict__ emb) {
    __shared__ float ws[8];
    const int j = blockIdx.x, tid = threadIdx.x;
    float2 x = *(const float2*)(emb + (size_t)j * EDIM + 2 * tid);
    float r = row_sumsq(x.x, x.y, ws, tid);
    if (tid == 0) {
        g_see[j]    = r;
        g_counts[j] = 0;
    }
}

__global__ void zz_kernel(const float* __restrict__ z) {
    __shared__ float ws[8];
    const int m = blockIdx.x, tid = threadIdx.x;
    const int n = m >> 9, t = m & 511;
    const float* base = z + (size_t)n * (EDIM * TDIM) + t;
    float x0 = base[(size_t)(2 * tid)     * TDIM];
    float x1 = base[(size_t)(2 * tid + 1) * TDIM];
    float r = row_sumsq(x0, x1, ws, tid);
    if (tid == 0) g_zz[m] = r;
}

// pre-round a float array to tf32 (float4 elementwise)
__global__ void cvt_kernel(const float* __restrict__ src,
                           float* __restrict__ dst) {
    int i = blockIdx.x * blockDim.x + threadIdx.x;
    float4 v = ((const float4*)src)[i];
    v.x = tf32r(v.x); v.y = tf32r(v.y);
    v.z = tf32r(v.z); v.w = tf32r(v.w);
    ((float4*)dst)[i] = v;
}

__global__ void init_kernel() {
    if (threadIdx.x == 0) g_loss = 0.0;
}

// ============================================================
// Kernel: TF32 tensor GEMM sweep, cp.async double-buffered.
//   d_hat = fl( see[j] - fl(acc+acc) )   (zz omitted: row-constant)
// stored as fp16 to g_dhat. mma sequence identical to R11 ->
// d_hat bitwise unchanged. Block tile 128x128, BK=16 x 2 buffers,
// 8 warps (4M x 2N), warp 32x64. grid = (2 halves, 128 row tiles)
// ============================================================
#define BK 16
#define AS_STRIDE 136
#define BS_STRIDE 20
#define NKT 32    // 512 / BK

__global__ __launch_bounds__(256)
void sweep_kernel(const float* __restrict__ zt,
                  const float* __restrict__ et) {
    __shared__ float As[2][BK][AS_STRIDE];    // [k][m]
    __shared__ float Bs[2][128][BS_STRIDE];   // [j][k]

    const int tid = threadIdx.x;
    const int h   = blockIdx.x;            // code half 0/1
    const int m0  = blockIdx.y * 128;      // row tile base
    const int nb  = m0 >> 9, t0 = m0 & 511;
    const float* zbase = zt + (size_t)nb * EDIM * TDIM + t0;

    const int warpId = tid >> 5, lane = tid & 31;
    const int warpRow = warpId >> 1, warpCol = warpId & 1;
    const int wm = warpRow * 32, wn = warpCol * 64;
    const int r  = lane >> 2,  tg = lane & 3;

    const int jh0 = h * (NE / 2);

    // staging ids (loop-invariant)
    const int ka0 = tid >> 5,       fa0 = tid & 31;        // A it=0
    const int ka1 = (tid + 256) >> 5, fa1 = tid & 31;      // A it=1
    const int jb0 = tid >> 2,       qb0 = tid & 3;         // B it=0
    const int jb1 = (tid + 256) >> 2, qb1 = tid & 3;       // B it=1

    for (int jt = 0; jt < 32; ++jt) {
        const int j0 = jh0 + jt * 128;
        float acc[2][8][4];
        #pragma unroll
        for (int am = 0; am < 2; am++)
            #pragma unroll
            for (int an = 0; an < 8; an++)
                #pragma unroll
                for (int q = 0; q < 4; q++) acc[am][an][q] = 0.f;

        // ---- stage chunk 0 into buffer 0 ----
        {
            const int e0 = 0;
            cp_async16(&As[0][ka0][fa0 * 4],
                       zbase + (size_t)(e0 + ka0) * TDIM + fa0 * 4);
            cp_async16(&As[0][ka1][fa1 * 4],
                       zbase + (size_t)(e0 + ka1) * TDIM + fa1 * 4);
            cp_async16(&Bs[0][jb0][qb0 * 4],
                       et + (size_t)(j0 + jb0) * EDIM + e0 + qb0 * 4);
            cp_async16(&Bs[0][jb1][qb1 * 4],
                       et + (size_t)(j0 + jb1) * EDIM + e0 + qb1 * 4);
            CP_COMMIT();
        }

        for (int kt = 0; kt < NKT; ++kt) {
            const int cur = kt & 1;
            if (kt + 1 < NKT) {
                const int e0 = (kt + 1) * BK;
                const int nxt = cur ^ 1;
                cp_async16(&As[nxt][ka0][fa0 * 4],
                           zbase + (size_t)(e0 + ka0) * TDIM + fa0 * 4);
                cp_async16(&As[nxt][ka1][fa1 * 4],
                           zbase + (size_t)(e0 + ka1) * TDIM + fa1 * 4);
                cp_async16(&Bs[nxt][jb0][qb0 * 4],
                           et + (size_t)(j0 + jb0) * EDIM + e0 + qb0 * 4);
                cp_async16(&Bs[nxt][jb1][qb1 * 4],
                           et + (size_t)(j0 + jb1) * EDIM + e0 + qb1 * 4);
                CP_COMMIT();
                CP_WAIT(1);
            } else {
                CP_WAIT(0);
            }
            __syncthreads();

            #pragma unroll
            for (int ks = 0; ks < 2; ++ks) {      // K ascending (frozen order)
                const int k8 = ks * 8;
                uint32_t a[2][4], b[8][2];
                #pragma unroll
                for (int am = 0; am < 2; ++am) {
                    int mb = wm + am * 16 + r;
                    a[am][0] = __float_as_uint(As[cur][k8 + tg    ][mb]);
                    a[am][1] = __float_as_uint(As[cur][k8 + tg    ][mb + 8]);
                    a[am][2] = __float_as_uint(As[cur][k8 + tg + 4][mb]);
                    a[am][3] = __float_as_uint(As[cur][k8 + tg + 4][mb + 8]);
                }
                #pragma unroll
                for (int an = 0; an < 8; ++an) {
                    int nf = wn + an * 8 + r;
                    b[an][0] = __float_as_uint(Bs[cur][nf][k8 + tg]);
                    b[an][1] = __float_as_uint(Bs[cur][nf][k8 + tg + 4]);
                }
                #pragma unroll
                for (int am = 0; am < 2; ++am)
                    #pragma unroll
                    for (int an = 0; an < 8; ++an)
                        mma_tf32(acc[am][an], a[am], b[an]);
            }
            __syncthreads();   // protect cur before it is restaged at kt+1
        }

        // epilogue: d_hat -> fp16 pair store (j, j+1 adjacent)
        #pragma unroll
        for (int an = 0; an < 8; ++an) {
            int nloc = wn + an * 8 + tg * 2;
            int j = j0 + nloc;
            float s0 = __ldg(&g_see[j]);
            float s1 = __ldg(&g_see[j + 1]);
            #pragma unroll
            for (int am = 0; am < 2; ++am) {
                #pragma unroll
                for (int half = 0; half < 2; ++half) {
                    int row = m0 + wm + am * 16 + half * 8 + r;
                    float g0 = acc[am][an][half * 2 + 0];
                    float g1 = acc[am][an][half * 2 + 1];
                    float d0 = __fsub_rn(s0, __fadd_rn(g0, g0));
                    float d1 = __fsub_rn(s1, __fadd_rn(g1, g1));
                    __half2 hh = __floats2half2_rn(d0, d1);
                    *(__half2*)(&g_dhat[(size_t)row * NE + j]) = hh;
                }
            }
        }
    }
}

// ============================================================
// Per-row min + candidate collection from stored d_hat.
// ============================================================
__global__ void cand_kernel() {
    __shared__ float ws[8];
    __shared__ float s_thr;
    __shared__ int   s_cnt;
    const int m = blockIdx.x, tid = threadIdx.x;
    const __half2* row = (const __half2*)(g_dhat + (size_t)m * NE);

    __half2 v[16];
    #pragma unroll
    for (int p = 0; p < 16; ++p) v[p] = row[tid + p * 256];

    float lmin = 3.4e38f;
    #pragma unroll
    for (int p = 0; p < 16; ++p) {
        float2 f = __half22float2(v[p]);
        lmin = fminf(lmin, fminf(f.x, f.y));
    }
    #pragma unroll
    for (int o = 16; o >= 1; o >>= 1)
        lmin = fminf(lmin, __shfl_xor_sync(0xffffffffu, lmin, o));
    if ((tid & 31) == 0) ws[tid >> 5] = lmin;
    __syncthreads();
    if (tid == 0) {
        float mn = ws[0];
        #pragma unroll
        for (int q = 1; q < 8; q++) mn = fminf(mn, ws[q]);
        s_thr = mn + MARGIN;
        s_cnt = 0;
    }
    __syncthreads();

    const float thr = s_thr;
    #pragma unroll
    for (int p = 0; p < 16; ++p) {
        float2 f = __half22float2(v[p]);
        int jbase = (tid + p * 256) * 2;
        if (f.x <= thr) {
            int pos = atomicAdd(&s_cnt, 1);
            if (pos < CAP) g_cand[m * CAP + pos] = jbase;
        }
        if (f.y <= thr) {
            int pos = atomicAdd(&s_cnt, 1);
            if (pos < CAP) g_cand[m * CAP + pos] = jbase + 1;
        }
    }
    __syncthreads();
    if (tid == 0) g_ccnt[m] = s_cnt;
}

// ============================================================
// Exact resolution: one warp/row, reference-exact serial ascending-K
// fp32 FMA chain + epilogue d = fl(fl(zz+see)-fl(g+g)); lexicographic
// (d, idx) min. Fallback full exact scan if cnt > CAP.
// ============================================================
__global__ void resolve_kernel(const float* __restrict__ z,
                               const float* __restrict__ emb) {
    const int tid = threadIdx.x;
    const int lane = tid & 31;
    const int m = blockIdx.x * 8 + (tid >> 5);
    const int n = m >> 9, t = m & 511;
    const float* zrow = z + (size_t)n * (EDIM * TDIM) + t;
    const float zz = __ldg(&g_zz[m]);
    const int cnt = g_ccnt[m];

    float bv = 3.4e38f;
    int   bi = 0x7fffffff;

    if (cnt <= CAP) {
        if (lane < cnt) {
            int j = g_cand[m * CAP + lane];
            const float* e = emb + (size_t)j * EDIM;
            float acc = 0.f;
            #pragma unroll 8
            for (int k = 0; k < EDIM; ++k)
                acc = __fmaf_rn(zrow[(size_t)k * TDIM], __ldg(&e[k]), acc);
            bv = __fsub_rn(__fadd_rn(zz, __ldg(&g_see[j])),
                           __fadd_rn(acc, acc));
            bi = j;
        }
    } else {
        for (int j = lane; j < NE; j += 32) {
            const float* e = emb + (size_t)j * EDIM;
            float acc = 0.f;
            #pragma unroll 8
            for (int k = 0; k < EDIM; ++k)
                acc = __fmaf_rn(zrow[(size_t)k * TDIM], __ldg(&e[k]), acc);
            float d = __fsub_rn(__fadd_rn(zz, __ldg(&g_see[j])),
                                __fadd_rn(acc, acc));
            if (d < bv || (d == bv && j < bi)) { bv = d; bi = j; }
        }
    }

    #pragma unroll
    for (int o = 16; o >= 1; o >>= 1) {
        float ov = __shfl_down_sync(0xffffffffu, bv, o);
        int   oi = __shfl_down_sync(0xffffffffu, bi, o);
        if (ov < bv || (ov == bv && oi < bi)) { bv = ov; bi = oi; }
    }
    if (lane == 0) {
        g_idx[m] = bi;
        atomicAdd(&g_counts[bi], 1);
    }
}

// ============================================================
// Straight-through output (reference's exact two rounding ops)
// + fp64 loss accumulation
// ============================================================
__global__ void output_loss_kernel(const float* __restrict__ z,
                                   const float* __restrict__ emb,
                                   float* __restrict__ out) {
    int g = blockIdx.x * blockDim.x + threadIdx.x;   // < NET exactly
    int t = g & (TDIM - 1);
    int e = (g >> 9) & (EDIM - 1);
    int n = g >> 18;
    int m = n * TDIM + t;
    int j = g_idx[m];
    float zf = z[g];
    float zq = __ldg(emb + (size_t)j * EDIM + e);
    float dsub = __fsub_rn(zq, zf);      // fl(z_q - zf)
    out[g] = __fadd_rn(zf, dsub);        // fl(zf + fl(z_q - zf))
    float sq = __fmul_rn(dsub, dsub);

    __shared__ float red[256];
    red[threadIdx.x] = sq;
    __syncthreads();
    #pragma unroll
    for (int s = 128; s > 0; s >>= 1) {
        if (threadIdx.x < s) red[threadIdx.x] += red[threadIdx.x + s];
        __syncthreads();
    }
    if (threadIdx.x == 0) atomicAdd(&g_loss, (double)red[0]);
}

// ============================================================
// Perplexity + scalars
// ============================================================
__global__ void scalar_kernel(float* __restrict__ out) {
    __shared__ double red[256];
    double s = 0.0;
    for (int j = threadIdx.x; j < NE; j += 256) {
        float em   = (float)g_counts[j] / (float)M_ROWS;
        float term = em * logf(em + 1e-10f);
        s += (double)term;
    }
    red[threadIdx.x] = s;
    __syncthreads();
    #pragma unroll
    for (int st = 128; st > 0; st >>= 1) {
        if (threadIdx.x < st) red[threadIdx.x] += red[threadIdx.x + st];
        __syncthreads();
    }
    if (threadIdx.x == 0) {
        double mean = g_loss / (double)((size_t)M_ROWS * EDIM);
        out[NET]     = (float)(1.25 * mean);       // (1 + BETA) * mean
        out[NET + 1] = expf((float)(-red[0]));     // perplexity
    }
}

// ============================================================
extern "C" void kernel_launch(void* const* d_in, const int* in_sizes, int n_in,
                              void* d_out, int out_size) {
    (void)in_sizes; (void)n_in; (void)out_size;
    const float* z   = (const float*)d_in[0];   // [N, E, T] fp32
    const float* emb = (const float*)d_in[1];   // [n_e, E] fp32
    float* out = (float*)d_out;

    float* zt; cudaGetSymbolAddress((void**)&zt, g_zt);
    float* et; cudaGetSymbolAddress((void**)&et, g_et);

    see_kernel<<<NE, 256>>>(emb);                       // 1
    zz_kernel<<<M_ROWS, 256>>>(z);                      // 2
    cvt_kernel<<<(NE * EDIM / 4) / 256, 256>>>(emb, et); // 3
    cvt_kernel<<<(NET / 4) / 256, 256>>>(z, zt);         // 4
    init_kernel<<<1, 32>>>();                           // 5

    dim3 g2(2, 128);
    sweep_kernel<<<g2, 256>>>(zt, et);                  // 6: GEMM (ncu slot)

    cand_kernel<<<M_ROWS, 256>>>();                     // 7
    resolve_kernel<<<M_ROWS / 8, 256>>>(z, emb);        // 8
    output_loss_kernel<<<NET / 256, 256>>>(z, emb, out); // 9
    scalar_kernel<<<1, 256>>>(out);                     // 10
}

// round 14
// speedup vs baseline: 1.1344x; 1.1344x over previous
#include <cuda_runtime.h>
#include <cuda_bf16.h>
#include <cuda_fp16.h>
#include <cstdint>

// Problem shape (fixed by the dataset instance)
#define NBATCH 32
#define EDIM   512
#define TDIM   512
#define M_ROWS 16384           // NBATCH*TDIM
#define NE     8192            // number of codes
#define NET    8388608         // NBATCH*EDIM*TDIM

#define CAP    64              // candidate cap per row
#define MARGIN 3e-3f           // >= 2*|d_hat err| (~9.4e-4 worst) + fp16 slop

// ---- scratch (__device__ globals; no allocations allowed) ----
__device__ float          g_zz[M_ROWS];
__device__ float          g_see[NE];
__device__ __nv_bfloat16  g_zb[(size_t)M_ROWS * EDIM];  // zf rows, bf16
__device__ __nv_bfloat16  g_eb[(size_t)NE * EDIM];      // emb rows, bf16
__device__ __half         g_dhat[(size_t)M_ROWS * NE];  // 268MB approx d
__device__ int            g_ccnt[M_ROWS];
__device__ int            g_cand[M_ROWS * CAP];
__device__ int            g_idx[M_ROWS];
__device__ int            g_counts[NE];
__device__ double         g_loss;

// m16n8k16 bf16 tensor-core MMA, fp32 accumulate (2x tf32-k8 MAC/instr)
__device__ __forceinline__ void mma_bf16(float* c,
                                         const uint32_t* a,
                                         const uint32_t* b) {
    asm volatile(
        "mma.sync.aligned.m16n8k16.row.col.f32.bf16.bf16.f32 "
        "{%0,%1,%2,%3}, {%4,%5,%6,%7}, {%8,%9}, {%0,%1,%2,%3};"
        : "+f"(c[0]), "+f"(c[1]), "+f"(c[2]), "+f"(c[3])
        : "r"(a[0]), "r"(a[1]), "r"(a[2]), "r"(a[3]),
          "r"(b[0]), "r"(b[1]));
}

// ============================================================
// Row sum-of-squares. FROZEN bit patterns (zz participates in the
// reference's tie bucketing; these exact kernels passed).
// ============================================================
__device__ __forceinline__ float row_sumsq(float x0, float x1,
                                           float* ws, int tid) {
    float v = __fadd_rn(__fmul_rn(x0, x0), __fmul_rn(x1, x1));
    #pragma unroll
    for (int o = 16; o >= 1; o >>= 1)
        v = __fadd_rn(v, __shfl_down_sync(0xffffffffu, v, o));
    if ((tid & 31) == 0) ws[tid >> 5] = v;
    __syncthreads();
    float r = 0.f;
    if (tid < 32) {
        float p = (tid < 8) ? ws[tid] : 0.f;
        #pragma unroll
        for (int o = 16; o >= 1; o >>= 1)
            p = __fadd_rn(p, __shfl_down_sync(0xffffffffu, p, o));
        r = p;
    }
    return r;
}

__global__ void see_kernel(const float* __restrict__ emb) {
    __shared__ float ws[8];
    const int j = blockIdx.x, tid = threadIdx.x;
    float2 x = *(const float2*)(emb + (size_t)j * EDIM + 2 * tid);
    float r = row_sumsq(x.x, x.y, ws, tid);
    if (tid == 0) {
        g_see[j]    = r;
        g_counts[j] = 0;
    }
}

__global__ void zz_kernel(const float* __restrict__ z) {
    __shared__ float ws[8];
    const int m = blockIdx.x, tid = threadIdx.x;
    const int n = m >> 9, t = m & 511;
    const float* base = z + (size_t)n * (EDIM * TDIM) + t;
    float x0 = base[(size_t)(2 * tid)     * TDIM];
    float x1 = base[(size_t)(2 * tid + 1) * TDIM];
    float r = row_sumsq(x0, x1, ws, tid);
    if (tid == 0) g_zz[m] = r;
}

// transpose z [n][k][t] -> zb[m=n*T+t][k] as bf16 (smem-tiled)
__global__ void zcvt_kernel(const float* __restrict__ z) {
    __shared__ float tile[32][33];
    const int n = blockIdx.z;
    const int k0 = blockIdx.x * 32, t0 = blockIdx.y * 32;
    const int tx = threadIdx.x, ty = threadIdx.y;     // block (32, 8)
    #pragma unroll
    for (int i = ty; i < 32; i += 8)
        tile[i][tx] = z[(size_t)n * (EDIM * TDIM) + (size_t)(k0 + i) * TDIM + t0 + tx];
    __syncthreads();
    #pragma unroll
    for (int i = ty; i < 32; i += 8)
        g_zb[(size_t)(n * TDIM + t0 + i) * EDIM + k0 + tx] =
            __float2bfloat16(tile[tx][i]);
}

// emb -> bf16 (elementwise)
__global__ void ecvt_kernel(const float* __restrict__ emb) {
    int i = blockIdx.x * blockDim.x + threadIdx.x;   // < NE*EDIM/4
    float4 v = ((const float4*)emb)[i];
    __nv_bfloat162* dst = (__nv_bfloat162*)g_eb;
    dst[2 * i]     = __floats2bfloat162_rn(v.x, v.y);
    dst[2 * i + 1] = __floats2bfloat162_rn(v.z, v.w);
}

__global__ void init_kernel() {
    if (threadIdx.x == 0) g_loss = 0.0;
}

// ============================================================
// Kernel: bf16 m16n8k16 tensor sweep.
//   d_hat = fl( see[j] - fl(acc+acc) )   (zz omitted: row-constant)
// stored fp16 to g_dhat. Block tile 128x128, BK=32 (2 k16 steps),
// 8 warps (4M x 2N), warp 32x64. A/B smem row-major bf16 with
// 40-bf16 row stride (20 b32 -> conflict-free fragment LDS).
// grid = (2 code halves, 128 row tiles)
// ============================================================
#define BK 32
#define S32 20     // smem row stride in b32 (= 40 bf16 = 80 bytes)
#define NKT 16     // 512 / BK

__global__ __launch_bounds__(256)
void sweep_kernel(const __nv_bfloat16* __restrict__ zb,
                  const __nv_bfloat16* __restrict__ eb) {
    __shared__ uint32_t sA[128 * S32];   // 10240 B
    __shared__ uint32_t sB[128 * S32];   // 10240 B

    const int tid = threadIdx.x;
    const int h   = blockIdx.x;            // code half 0/1
    const int m0  = blockIdx.y * 128;      // row tile base

    const int warpId = tid >> 5, lane = tid & 31;
    const int warpRow = warpId >> 1, warpCol = warpId & 1;
    const int wm = warpRow * 32, wn = warpCol * 64;
    const int r  = lane >> 2,  tg = lane & 3;

    const int jh0 = h * (NE / 2);

    // staging ids: id 0..511 -> row = id>>2, 16B granule gq = id&3
    const int row0 = tid >> 2,           gq0 = tid & 3;
    const int row1 = (tid + 256) >> 2,   gq1 = tid & 3;

    for (int jt = 0; jt < 32; ++jt) {
        const int j0 = jh0 + jt * 128;
        float acc[2][8][4];
        #pragma unroll
        for (int am = 0; am < 2; am++)
            #pragma unroll
            for (int an = 0; an < 8; an++)
                #pragma unroll
                for (int q = 0; q < 4; q++) acc[am][an][q] = 0.f;

        for (int kt = 0; kt < NKT; ++kt) {
            const int e0 = kt * BK;
            // stage A: 128 rows x 32 bf16 (64B/row, 4 x 16B granules)
            {
                uint4 va0 = *(const uint4*)(zb + (size_t)(m0 + row0) * EDIM + e0 + gq0 * 8);
                uint4 va1 = *(const uint4*)(zb + (size_t)(m0 + row1) * EDIM + e0 + gq1 * 8);
                ((uint4*)sA)[row0 * 5 + gq0] = va0;
                ((uint4*)sA)[row1 * 5 + gq1] = va1;
                uint4 vb0 = *(const uint4*)(eb + (size_t)(j0 + row0) * EDIM + e0 + gq0 * 8);
                uint4 vb1 = *(const uint4*)(eb + (size_t)(j0 + row1) * EDIM + e0 + gq1 * 8);
                ((uint4*)sB)[row0 * 5 + gq0] = vb0;
                ((uint4*)sB)[row1 * 5 + gq1] = vb1;
            }
            __syncthreads();

            #pragma unroll
            for (int ks = 0; ks < 2; ++ks) {          // two k16 steps
                const int ko = ks * 8;                // b32 offset within row
                uint32_t a[2][4], b[8][2];
                #pragma unroll
                for (int am = 0; am < 2; ++am) {
                    int mb = (wm + am * 16 + r) * S32 + ko + tg;
                    a[am][0] = sA[mb];                // A[g][2t..2t+1]
                    a[am][1] = sA[mb + 8 * S32];      // A[g+8][2t..]
                    a[am][2] = sA[mb + 4];            // A[g][2t+8..]
                    a[am][3] = sA[mb + 8 * S32 + 4];  // A[g+8][2t+8..]
                }
                #pragma unroll
                for (int an = 0; an < 8; ++an) {
                    int nb = (wn + an * 8 + r) * S32 + ko + tg;
                    b[an][0] = sB[nb];                // B[col g][2t..]
                    b[an][1] = sB[nb + 4];            // B[col g][2t+8..]
                }
                #pragma unroll
                for (int am = 0; am < 2; ++am)
                    #pragma unroll
                    for (int an = 0; an < 8; ++an)
                        mma_bf16(acc[am][an], a[am], b[an]);
            }
            __syncthreads();
        }

        // epilogue: d_hat -> fp16 pair store (j, j+1 adjacent)
        #pragma unroll
        for (int an = 0; an < 8; ++an) {
            int nloc = wn + an * 8 + tg * 2;
            int j = j0 + nloc;
            float s0 = __ldg(&g_see[j]);
            float s1 = __ldg(&g_see[j + 1]);
            #pragma unroll
            for (int am = 0; am < 2; ++am) {
                #pragma unroll
                for (int half = 0; half < 2; ++half) {
                    int row = m0 + wm + am * 16 + half * 8 + r;
                    float g0 = acc[am][an][half * 2 + 0];
                    float g1 = acc[am][an][half * 2 + 1];
                    float d0 = __fsub_rn(s0, __fadd_rn(g0, g0));
                    float d1 = __fsub_rn(s1, __fadd_rn(g1, g1));
                    __half2 hh = __floats2half2_rn(d0, d1);
                    *(__half2*)(&g_dhat[(size_t)row * NE + j]) = hh;
                }
            }
        }
    }
}

// ============================================================
// Per-row min + candidate collection from stored d_hat.
// ============================================================
__global__ void cand_kernel() {
    __shared__ float ws[8];
    __shared__ float s_thr;
    __shared__ int   s_cnt;
    const int m = blockIdx.x, tid = threadIdx.x;
    const __half2* row = (const __half2*)(g_dhat + (size_t)m * NE);

    __half2 v[16];
    #pragma unroll
    for (int p = 0; p < 16; ++p) v[p] = row[tid + p * 256];

    float lmin = 3.4e38f;
    #pragma unroll
    for (int p = 0; p < 16; ++p) {
        float2 f = __half22float2(v[p]);
        lmin = fminf(lmin, fminf(f.x, f.y));
    }
    #pragma unroll
    for (int o = 16; o >= 1; o >>= 1)
        lmin = fminf(lmin, __shfl_xor_sync(0xffffffffu, lmin, o));
    if ((tid & 31) == 0) ws[tid >> 5] = lmin;
    __syncthreads();
    if (tid == 0) {
        float mn = ws[0];
        #pragma unroll
        for (int q = 1; q < 8; q++) mn = fminf(mn, ws[q]);
        s_thr = mn + MARGIN;
        s_cnt = 0;
    }
    __syncthreads();

    const float thr = s_thr;
    #pragma unroll
    for (int p = 0; p < 16; ++p) {
        float2 f = __half22float2(v[p]);
        int jbase = (tid + p * 256) * 2;
        if (f.x <= thr) {
            int pos = atomicAdd(&s_cnt, 1);
            if (pos < CAP) g_cand[m * CAP + pos] = jbase;
        }
        if (f.y <= thr) {
            int pos = atomicAdd(&s_cnt, 1);
            if (pos < CAP) g_cand[m * CAP + pos] = jbase + 1;
        }
    }
    __syncthreads();
    if (tid == 0) g_ccnt[m] = s_cnt;
}

// ============================================================
// Exact resolution: one warp/row, reference-exact serial ascending-K
// fp32 FMA chain + epilogue d = fl(fl(zz+see)-fl(g+g)); lexicographic
// (d, idx) min. Fallback full exact scan if cnt > CAP.
// ============================================================
__global__ void resolve_kernel(const float* __restrict__ z,
                               const float* __restrict__ emb) {
    const int tid = threadIdx.x;
    const int lane = tid & 31;
    const int m = blockIdx.x * 8 + (tid >> 5);
    const int n = m >> 9, t = m & 511;
    const float* zrow = z + (size_t)n * (EDIM * TDIM) + t;
    const float zz = __ldg(&g_zz[m]);
    const int cnt = g_ccnt[m];

    float bv = 3.4e38f;
    int   bi = 0x7fffffff;

    if (cnt <= CAP) {
        for (int c = lane; c < cnt; c += 32) {
            int j = g_cand[m * CAP + c];
            const float* e = emb + (size_t)j * EDIM;
            float acc = 0.f;
            #pragma unroll 8
            for (int k = 0; k < EDIM; ++k)
                acc = __fmaf_rn(zrow[(size_t)k * TDIM], __ldg(&e[k]), acc);
            float d = __fsub_rn(__fadd_rn(zz, __ldg(&g_see[j])),
                                __fadd_rn(acc, acc));
            if (d < bv || (d == bv && j < bi)) { bv = d; bi = j; }
        }
    } else {
        for (int j = lane; j < NE; j += 32) {
            const float* e = emb + (size_t)j * EDIM;
            float acc = 0.f;
            #pragma unroll 8
            for (int k = 0; k < EDIM; ++k)
                acc = __fmaf_rn(zrow[(size_t)k * TDIM], __ldg(&e[k]), acc);
            float d = __fsub_rn(__fadd_rn(zz, __ldg(&g_see[j])),
                                __fadd_rn(acc, acc));
            if (d < bv || (d == bv && j < bi)) { bv = d; bi = j; }
        }
    }

    #pragma unroll
    for (int o = 16; o >= 1; o >>= 1) {
        float ov = __shfl_down_sync(0xffffffffu, bv, o);
        int   oi = __shfl_down_sync(0xffffffffu, bi, o);
        if (ov < bv || (ov == bv && oi < bi)) { bv = ov; bi = oi; }
    }
    if (lane == 0) {
        g_idx[m] = bi;
        atomicAdd(&g_counts[bi], 1);
    }
}

// ============================================================
// Straight-through output (reference's exact two rounding ops ->
// bitwise output with matching idx) + fp64 loss accumulation
// ============================================================
__global__ void output_loss_kernel(const float* __restrict__ z,
                                   const float* __restrict__ emb,
                                   float* __restrict__ out) {
    int g = blockIdx.x * blockDim.x + threadIdx.x;   // < NET exactly
    int t = g & (TDIM - 1);
    int e = (g >> 9) & (EDIM - 1);
    int n = g >> 18;
    int m = n * TDIM + t;
    int j = g_idx[m];
    float zf = z[g];
    float zq = __ldg(emb + (size_t)j * EDIM + e);
    float dsub = __fsub_rn(zq, zf);      // fl(z_q - zf)
    out[g] = __fadd_rn(zf, dsub);        // fl(zf + fl(z_q - zf))
    float sq = __fmul_rn(dsub, dsub);

    __shared__ float red[256];
    red[threadIdx.x] = sq;
    __syncthreads();
    #pragma unroll
    for (int s = 128; s > 0; s >>= 1) {
        if (threadIdx.x < s) red[threadIdx.x] += red[threadIdx.x + s];
        __syncthreads();
    }
    if (threadIdx.x == 0) atomicAdd(&g_loss, (double)red[0]);
}

// ============================================================
// Perplexity + scalars
// ============================================================
__global__ void scalar_kernel(float* __restrict__ out) {
    __shared__ double red[256];
    double s = 0.0;
    for (int j = threadIdx.x; j < NE; j += 256) {
        float em   = (float)g_counts[j] / (float)M_ROWS;
        float term = em * logf(em + 1e-10f);
        s += (double)term;
    }
    red[threadIdx.x] = s;
    __syncthreads();
    #pragma unroll
    for (int st = 128; st > 0; st >>= 1) {
        if (threadIdx.x < st) red[threadIdx.x] += red[threadIdx.x + st];
        __syncthreads();
    }
    if (threadIdx.x == 0) {
        double mean = g_loss / (double)((size_t)M_ROWS * EDIM);
        out[NET]     = (float)(1.25 * mean);       // (1 + BETA) * mean
        out[NET + 1] = expf((float)(-red[0]));     // perplexity
    }
}

// ============================================================
extern "C" void kernel_launch(void* const* d_in, const int* in_sizes, int n_in,
                              void* d_out, int out_size) {
    (void)in_sizes; (void)n_in; (void)out_size;
    const float* z   = (const float*)d_in[0];   // [N, E, T] fp32
    const float* emb = (const float*)d_in[1];   // [n_e, E] fp32
    float* out = (float*)d_out;

    __nv_bfloat16* zb; cudaGetSymbolAddress((void**)&zb, g_zb);
    __nv_bfloat16* eb; cudaGetSymbolAddress((void**)&eb, g_eb);

    see_kernel<<<NE, 256>>>(emb);                        // 1
    zz_kernel<<<M_ROWS, 256>>>(z);                       // 2
    ecvt_kernel<<<(NE * EDIM / 4) / 256, 256>>>(emb);    // 3
    zcvt_kernel<<<dim3(16, 16, 32), dim3(32, 8)>>>(z);   // 4
    init_kernel<<<1, 32>>>();                            // 5

    dim3 g2(2, 128);                                     // (halves, m-tiles)
    sweep_kernel<<<g2, 256>>>(zb, eb);                   // 6: bf16 mma sweep

    cand_kernel<<<M_ROWS, 256>>>();                      // 7
    resolve_kernel<<<M_ROWS / 8, 256>>>(z, emb);         // 8
    output_loss_kernel<<<NET / 256, 256>>>(z, emb, out); // 9
    scalar_kernel<<<1, 256>>>(out);                      // 10
}

// round 15
// speedup vs baseline: 1.3025x; 1.1482x over previous
#include <cuda_runtime.h>
#include <cuda_bf16.h>
#include <cuda_fp16.h>
#include <cstdint>

// Problem shape (fixed by the dataset instance)
#define NBATCH 32
#define EDIM   512
#define TDIM   512
#define M_ROWS 16384           // NBATCH*TDIM
#define NE     8192            // number of codes
#define NET    8388608         // NBATCH*EDIM*TDIM

#define CAP    64              // candidate cap per row
#define MARGIN 3e-3f           // >= 2*|d_hat err| (~9.4e-4 worst) + fp16 slop

// ---- scratch (__device__ globals; no allocations allowed) ----
__device__ float          g_zz[M_ROWS];
__device__ float          g_see[NE];
__device__ __nv_bfloat16  g_zb[(size_t)M_ROWS * EDIM];  // zf rows, bf16
__device__ __nv_bfloat16  g_eb[(size_t)NE * EDIM];      // emb rows, bf16
__device__ __half         g_dhat[(size_t)M_ROWS * NE];  // 268MB approx d
__device__ int            g_ccnt[M_ROWS];
__device__ int            g_cand[M_ROWS * CAP];
__device__ int            g_idx[M_ROWS];
__device__ int            g_counts[NE];
__device__ double         g_loss;

// m16n8k16 bf16 tensor-core MMA, fp32 accumulate
__device__ __forceinline__ void mma_bf16(float* c,
                                         const uint32_t* a,
                                         const uint32_t* b) {
    asm volatile(
        "mma.sync.aligned.m16n8k16.row.col.f32.bf16.bf16.f32 "
        "{%0,%1,%2,%3}, {%4,%5,%6,%7}, {%8,%9}, {%0,%1,%2,%3};"
        : "+f"(c[0]), "+f"(c[1]), "+f"(c[2]), "+f"(c[3])
        : "r"(a[0]), "r"(a[1]), "r"(a[2]), "r"(a[3]),
          "r"(b[0]), "r"(b[1]));
}

__device__ __forceinline__ void ldsm_x4(uint32_t& r0, uint32_t& r1,
                                        uint32_t& r2, uint32_t& r3,
                                        uint32_t addr) {
    asm volatile(
        "ldmatrix.sync.aligned.m8n8.x4.shared.b16 {%0,%1,%2,%3}, [%4];"
        : "=r"(r0), "=r"(r1), "=r"(r2), "=r"(r3) : "r"(addr));
}

__device__ __forceinline__ void cp16(uint32_t smem, const void* gmem) {
    asm volatile("cp.async.cg.shared.global [%0], [%1], 16;"
                 :: "r"(smem), "l"(gmem));
}
#define CP_COMMIT() asm volatile("cp.async.commit_group;")
#define CP_WAIT(n)  asm volatile("cp.async.wait_group %0;" :: "n"(n))

// ============================================================
// Row sum-of-squares. FROZEN bit patterns (zz participates in the
// reference's tie bucketing; these exact kernels passed).
// ============================================================
__device__ __forceinline__ float row_sumsq(float x0, float x1,
                                           float* ws, int tid) {
    float v = __fadd_rn(__fmul_rn(x0, x0), __fmul_rn(x1, x1));
    #pragma unroll
    for (int o = 16; o >= 1; o >>= 1)
        v = __fadd_rn(v, __shfl_down_sync(0xffffffffu, v, o));
    if ((tid & 31) == 0) ws[tid >> 5] = v;
    __syncthreads();
    float r = 0.f;
    if (tid < 32) {
        float p = (tid < 8) ? ws[tid] : 0.f;
        #pragma unroll
        for (int o = 16; o >= 1; o >>= 1)
            p = __fadd_rn(p, __shfl_down_sync(0xffffffffu, p, o));
        r = p;
    }
    return r;
}

__global__ void see_kernel(const float* __restrict__ emb) {
    __shared__ float ws[8];
    const int j = blockIdx.x, tid = threadIdx.x;
    float2 x = *(const float2*)(emb + (size_t)j * EDIM + 2 * tid);
    float r = row_sumsq(x.x, x.y, ws, tid);
    if (tid == 0) {
        g_see[j]    = r;
        g_counts[j] = 0;
    }
}

__global__ void zz_kernel(const float* __restrict__ z) {
    __shared__ float ws[8];
    const int m = blockIdx.x, tid = threadIdx.x;
    const int n = m >> 9, t = m & 511;
    const float* base = z + (size_t)n * (EDIM * TDIM) + t;
    float x0 = base[(size_t)(2 * tid)     * TDIM];
    float x1 = base[(size_t)(2 * tid + 1) * TDIM];
    float r = row_sumsq(x0, x1, ws, tid);
    if (tid == 0) g_zz[m] = r;
}

// transpose z [n][k][t] -> zb[m=n*T+t][k] as bf16 (smem-tiled)
__global__ void zcvt_kernel(const float* __restrict__ z) {
    __shared__ float tile[32][33];
    const int n = blockIdx.z;
    const int k0 = blockIdx.x * 32, t0 = blockIdx.y * 32;
    const int tx = threadIdx.x, ty = threadIdx.y;     // block (32, 8)
    #pragma unroll
    for (int i = ty; i < 32; i += 8)
        tile[i][tx] = z[(size_t)n * (EDIM * TDIM) + (size_t)(k0 + i) * TDIM + t0 + tx];
    __syncthreads();
    #pragma unroll
    for (int i = ty; i < 32; i += 8)
        g_zb[(size_t)(n * TDIM + t0 + i) * EDIM + k0 + tx] =
            __float2bfloat16(tile[tx][i]);
}

// emb -> bf16 (elementwise)
__global__ void ecvt_kernel(const float* __restrict__ emb) {
    int i = blockIdx.x * blockDim.x + threadIdx.x;   // < NE*EDIM/4
    float4 v = ((const float4*)emb)[i];
    __nv_bfloat162* dst = (__nv_bfloat162*)g_eb;
    dst[2 * i]     = __floats2bfloat162_rn(v.x, v.y);
    dst[2 * i + 1] = __floats2bfloat162_rn(v.z, v.w);
}

__global__ void init_kernel() {
    if (threadIdx.x == 0) g_loss = 0.0;
}

// ============================================================
// Kernel: bf16 m16n8k16 tensor sweep with ldmatrix fragment loads
// and cp.async double-buffered staging.
//   d_hat = fl( see[j] - fl(acc+acc) )   (zz omitted: row-constant)
// Block tile 128x128, BK=32 (2 k16 steps), 8 warps (4M x 2N),
// warp 32x64. smem rows: 40 bf16 stride (80B) -> LDSM conflict-free.
// grid = (2 code halves, 128 row tiles)
// ============================================================
#define BK 32
#define ROWB 80          // smem row stride in bytes (40 bf16)
#define STAGE_B (128 * ROWB)   // 10240 B per operand per stage
#define NKT 16           // 512 / BK

__global__ __launch_bounds__(256)
void sweep_kernel(const __nv_bfloat16* __restrict__ zb,
                  const __nv_bfloat16* __restrict__ eb) {
    __shared__ __align__(16) uint8_t sA[2 * STAGE_B];
    __shared__ __align__(16) uint8_t sB[2 * STAGE_B];

    const int tid = threadIdx.x;
    const int h   = blockIdx.x;            // code half 0/1
    const int m0  = blockIdx.y * 128;      // row tile base

    const int warpId = tid >> 5, lane = tid & 31;
    const int warpRow = warpId >> 1, warpCol = warpId & 1;
    const int wm = warpRow * 32, wn = warpCol * 64;
    const int r  = lane >> 2,  tg = lane & 3;

    const uint32_t sA32 = (uint32_t)__cvta_generic_to_shared(sA);
    const uint32_t sB32 = (uint32_t)__cvta_generic_to_shared(sB);

    // ldmatrix per-lane source addresses (byte offsets within a stage)
    // A x4 (per am): mat0 rows g k0-7 | mat1 rows g+8 k0-7
    //                mat2 rows g k8-15 | mat3 rows g+8 k8-15
    const int arow = (lane & 7) + ((lane >> 3) & 1) * 8;   // row within 16
    const int akg  = (lane >> 4) & 1;                      // k granule
    const uint32_t aoff = (uint32_t)((wm + arow) * ROWB + akg * 16);
    // B x4 (per an-pair): mat0 n(an) k0 | mat1 n(an) k8
    //                     mat2 n(an+1) k0 | mat3 n(an+1) k8
    const int brow = (lane & 7) + ((lane >> 4) & 1) * 8;   // n within pair
    const int bkg  = (lane >> 3) & 1;
    const uint32_t boff = (uint32_t)((wn + brow) * ROWB + bkg * 16);

    // staging ids: id 0..511 -> row = id>>2, 16B granule gq = id&3
    const int row0 = tid >> 2,         gq0 = tid & 3;
    const int row1 = (tid + 256) >> 2, gq1 = tid & 3;
    const uint32_t st0 = (uint32_t)(row0 * ROWB + gq0 * 16);
    const uint32_t st1 = (uint32_t)(row1 * ROWB + gq1 * 16);

    const int jh0 = h * (NE / 2);

    for (int jt = 0; jt < 32; ++jt) {
        const int j0 = jh0 + jt * 128;
        float acc[2][8][4];
        #pragma unroll
        for (int am = 0; am < 2; am++)
            #pragma unroll
            for (int an = 0; an < 8; an++)
                #pragma unroll
                for (int q = 0; q < 4; q++) acc[am][an][q] = 0.f;

        // prefetch chunk 0 into stage 0
        {
            const __nv_bfloat16* za = zb + (size_t)m0 * EDIM;
            const __nv_bfloat16* ea = eb + (size_t)j0 * EDIM;
            cp16(sA32 + st0, za + (size_t)row0 * EDIM + gq0 * 8);
            cp16(sA32 + st1, za + (size_t)row1 * EDIM + gq1 * 8);
            cp16(sB32 + st0, ea + (size_t)row0 * EDIM + gq0 * 8);
            cp16(sB32 + st1, ea + (size_t)row1 * EDIM + gq1 * 8);
            CP_COMMIT();
        }

        for (int kt = 0; kt < NKT; ++kt) {
            const uint32_t cb = (uint32_t)(kt & 1) * STAGE_B;   // current
            if (kt + 1 < NKT) {
                const int e0 = (kt + 1) * BK;
                const uint32_t nb = (uint32_t)((kt + 1) & 1) * STAGE_B;
                const __nv_bfloat16* za = zb + (size_t)m0 * EDIM + e0;
                const __nv_bfloat16* ea = eb + (size_t)j0 * EDIM + e0;
                cp16(sA32 + nb + st0, za + (size_t)row0 * EDIM + gq0 * 8);
                cp16(sA32 + nb + st1, za + (size_t)row1 * EDIM + gq1 * 8);
                cp16(sB32 + nb + st0, ea + (size_t)row0 * EDIM + gq0 * 8);
                cp16(sB32 + nb + st1, ea + (size_t)row1 * EDIM + gq1 * 8);
                CP_COMMIT();
                CP_WAIT(1);
            } else {
                CP_WAIT(0);
            }
            __syncthreads();

            #pragma unroll
            for (int ks = 0; ks < 2; ++ks) {          // two k16 steps
                const uint32_t ko = (uint32_t)(ks * 32);   // bytes
                uint32_t a[2][4], b[8][2];
                ldsm_x4(a[0][0], a[0][1], a[0][2], a[0][3],
                        sA32 + cb + aoff + ko);
                ldsm_x4(a[1][0], a[1][1], a[1][2], a[1][3],
                        sA32 + cb + aoff + ko + 16 * ROWB);
                #pragma unroll
                for (int p = 0; p < 4; ++p)
                    ldsm_x4(b[2 * p][0], b[2 * p][1],
                            b[2 * p + 1][0], b[2 * p + 1][1],
                            sB32 + cb + boff + ko + (uint32_t)(p * 16 * ROWB));
                #pragma unroll
                for (int am = 0; am < 2; ++am)
                    #pragma unroll
                    for (int an = 0; an < 8; ++an)
                        mma_bf16(acc[am][an], a[am], b[an]);
            }
            __syncthreads();   // cur fully consumed before restage at kt+1
        }

        // epilogue: d_hat -> fp16 pair store (j, j+1 adjacent)
        #pragma unroll
        for (int an = 0; an < 8; ++an) {
            int nloc = wn + an * 8 + tg * 2;
            int j = j0 + nloc;
            float s0 = __ldg(&g_see[j]);
            float s1 = __ldg(&g_see[j + 1]);
            #pragma unroll
            for (int am = 0; am < 2; ++am) {
                #pragma unroll
                for (int half = 0; half < 2; ++half) {
                    int row = m0 + wm + am * 16 + half * 8 + r;
                    float g0 = acc[am][an][half * 2 + 0];
                    float g1 = acc[am][an][half * 2 + 1];
                    float d0 = __fsub_rn(s0, __fadd_rn(g0, g0));
                    float d1 = __fsub_rn(s1, __fadd_rn(g1, g1));
                    __half2 hh = __floats2half2_rn(d0, d1);
                    *(__half2*)(&g_dhat[(size_t)row * NE + j]) = hh;
                }
            }
        }
    }
}

// ============================================================
// Per-row min + candidate collection from stored d_hat.
// ============================================================
__global__ void cand_kernel() {
    __shared__ float ws[8];
    __shared__ float s_thr;
    __shared__ int   s_cnt;
    const int m = blockIdx.x, tid = threadIdx.x;
    const __half2* row = (const __half2*)(g_dhat + (size_t)m * NE);

    __half2 v[16];
    #pragma unroll
    for (int p = 0; p < 16; ++p) v[p] = row[tid + p * 256];

    float lmin = 3.4e38f;
    #pragma unroll
    for (int p = 0; p < 16; ++p) {
        float2 f = __half22float2(v[p]);
        lmin = fminf(lmin, fminf(f.x, f.y));
    }
    #pragma unroll
    for (int o = 16; o >= 1; o >>= 1)
        lmin = fminf(lmin, __shfl_xor_sync(0xffffffffu, lmin, o));
    if ((tid & 31) == 0) ws[tid >> 5] = lmin;
    __syncthreads();
    if (tid == 0) {
        float mn = ws[0];
        #pragma unroll
        for (int q = 1; q < 8; q++) mn = fminf(mn, ws[q]);
        s_thr = mn + MARGIN;
        s_cnt = 0;
    }
    __syncthreads();

    const float thr = s_thr;
    #pragma unroll
    for (int p = 0; p < 16; ++p) {
        float2 f = __half22float2(v[p]);
        int jbase = (tid + p * 256) * 2;
        if (f.x <= thr) {
            int pos = atomicAdd(&s_cnt, 1);
            if (pos < CAP) g_cand[m * CAP + pos] = jbase;
        }
        if (f.y <= thr) {
            int pos = atomicAdd(&s_cnt, 1);
            if (pos < CAP) g_cand[m * CAP + pos] = jbase + 1;
        }
    }
    __syncthreads();
    if (tid == 0) g_ccnt[m] = s_cnt;
}

// ============================================================
// Exact resolution: one warp/row, reference-exact serial ascending-K
// fp32 FMA chain + epilogue d = fl(fl(zz+see)-fl(g+g)); lexicographic
// (d, idx) min. Fallback full exact scan if cnt > CAP.
// ============================================================
__global__ void resolve_kernel(const float* __restrict__ z,
                               const float* __restrict__ emb) {
    const int tid = threadIdx.x;
    const int lane = tid & 31;
    const int m = blockIdx.x * 8 + (tid >> 5);
    const int n = m >> 9, t = m & 511;
    const float* zrow = z + (size_t)n * (EDIM * TDIM) + t;
    const float zz = __ldg(&g_zz[m]);
    const int cnt = g_ccnt[m];

    float bv = 3.4e38f;
    int   bi = 0x7fffffff;

    if (cnt <= CAP) {
        for (int c = lane; c < cnt; c += 32) {
            int j = g_cand[m * CAP + c];
            const float* e = emb + (size_t)j * EDIM;
            float acc = 0.f;
            #pragma unroll 8
            for (int k = 0; k < EDIM; ++k)
                acc = __fmaf_rn(zrow[(size_t)k * TDIM], __ldg(&e[k]), acc);
            float d = __fsub_rn(__fadd_rn(zz, __ldg(&g_see[j])),
                                __fadd_rn(acc, acc));
            if (d < bv || (d == bv && j < bi)) { bv = d; bi = j; }
        }
    } else {
        for (int j = lane; j < NE; j += 32) {
            const float* e = emb + (size_t)j * EDIM;
            float acc = 0.f;
            #pragma unroll 8
            for (int k = 0; k < EDIM; ++k)
                acc = __fmaf_rn(zrow[(size_t)k * TDIM], __ldg(&e[k]), acc);
            float d = __fsub_rn(__fadd_rn(zz, __ldg(&g_see[j])),
                                __fadd_rn(acc, acc));
            if (d < bv || (d == bv && j < bi)) { bv = d; bi = j; }
        }
    }

    #pragma unroll
    for (int o = 16; o >= 1; o >>= 1) {
        float ov = __shfl_down_sync(0xffffffffu, bv, o);
        int   oi = __shfl_down_sync(0xffffffffu, bi, o);
        if (ov < bv || (ov == bv && oi < bi)) { bv = ov; bi = oi; }
    }
    if (lane == 0) {
        g_idx[m] = bi;
        atomicAdd(&g_counts[bi], 1);
    }
}

// ============================================================
// Straight-through output (reference's exact two rounding ops ->
// bitwise output with matching idx) + fp64 loss accumulation
// ============================================================
__global__ void output_loss_kernel(const float* __restrict__ z,
                                   const float* __restrict__ emb,
                                   float* __restrict__ out) {
    int g = blockIdx.x * blockDim.x + threadIdx.x;   // < NET exactly
    int t = g & (TDIM - 1);
    int e = (g >> 9) & (EDIM - 1);
    int n = g >> 18;
    int m = n * TDIM + t;
    int j = g_idx[m];
    float zf = z[g];
    float zq = __ldg(emb + (size_t)j * EDIM + e);
    float dsub = __fsub_rn(zq, zf);      // fl(z_q - zf)
    out[g] = __fadd_rn(zf, dsub);        // fl(zf + fl(z_q - zf))
    float sq = __fmul_rn(dsub, dsub);

    __shared__ float red[256];
    red[threadIdx.x] = sq;
    __syncthreads();
    #pragma unroll
    for (int s = 128; s > 0; s >>= 1) {
        if (threadIdx.x < s) red[threadIdx.x] += red[threadIdx.x + s];
        __syncthreads();
    }
    if (threadIdx.x == 0) atomicAdd(&g_loss, (double)red[0]);
}

// ============================================================
// Perplexity + scalars
// ============================================================
__global__ void scalar_kernel(float* __restrict__ out) {
    __shared__ double red[256];
    double s = 0.0;
    for (int j = threadIdx.x; j < NE; j += 256) {
        float em   = (float)g_counts[j] / (float)M_ROWS;
        float term = em * logf(em + 1e-10f);
        s += (double)term;
    }
    red[threadIdx.x] = s;
    __syncthreads();
    #pragma unroll
    for (int st = 128; st > 0; st >>= 1) {
        if (threadIdx.x < st) red[threadIdx.x] += red[threadIdx.x + st];
        __syncthreads();
    }
    if (threadIdx.x == 0) {
        double mean = g_loss / (double)((size_t)M_ROWS * EDIM);
        out[NET]     = (float)(1.25 * mean);       // (1 + BETA) * mean
        out[NET + 1] = expf((float)(-red[0]));     // perplexity
    }
}

// ============================================================
extern "C" void kernel_launch(void* const* d_in, const int* in_sizes, int n_in,
                              void* d_out, int out_size) {
    (void)in_sizes; (void)n_in; (void)out_size;
    const float* z   = (const float*)d_in[0];   // [N, E, T] fp32
    const float* emb = (const float*)d_in[1];   // [n_e, E] fp32
    float* out = (float*)d_out;

    __nv_bfloat16* zb; cudaGetSymbolAddress((void**)&zb, g_zb);
    __nv_bfloat16* eb; cudaGetSymbolAddress((void**)&eb, g_eb);

    see_kernel<<<NE, 256>>>(emb);                        // 1
    zz_kernel<<<M_ROWS, 256>>>(z);                       // 2
    ecvt_kernel<<<(NE * EDIM / 4) / 256, 256>>>(emb);    // 3
    zcvt_kernel<<<dim3(16, 16, 32), dim3(32, 8)>>>(z);   // 4
    init_kernel<<<1, 32>>>();                            // 5

    dim3 g2(2, 128);                                     // (halves, m-tiles)
    sweep_kernel<<<g2, 256>>>(zb, eb);                   // 6: bf16 mma sweep

    cand_kernel<<<M_ROWS, 256>>>();                      // 7
    resolve_kernel<<<M_ROWS / 8, 256>>>(z, emb);         // 8
    output_loss_kernel<<<NET / 256, 256>>>(z, emb, out); // 9
    scalar_kernel<<<1, 256>>>(out);                      // 10
}